// round 5
// baseline (speedup 1.0000x reference)
#include <cuda_runtime.h>

#define NB 16
#define L 768
#define D 128
#define L3 256          // L / CLIP
#define KD 384          // CLIP * D
#define INV_T 0.08838834764831845f   // 1/sqrt(128)

// scratch (allocation-free rule: __device__ globals)
__device__ float g_Lb[NB * L3 * L3];   // [b][i][j]

// ---------------------------------------------------------------------------
// Kernel 1: local block GEMM with fc-weight folding fused into the A loader.
// Lb[b,i,j] = sum_{c,d} qw[b,i,c,d] * kflat[b,j,c,d] + 128*fc_b
// ---------------------------------------------------------------------------
__global__ __launch_bounds__(256) void lb_kernel(const float* __restrict__ q,
                                                 const float* __restrict__ k,
                                                 const float* __restrict__ fc_w,
                                                 const float* __restrict__ fc_b) {
    __shared__ float sA[64][65];
    __shared__ float sB[64][65];
    const int b  = blockIdx.z;
    const int i0 = blockIdx.y * 64;
    const int j0 = blockIdx.x * 64;
    const int tid = threadIdx.x;
    const int txn = tid & 15;    // n dim
    const int tym = tid >> 4;    // m dim

    float w[9];
    #pragma unroll
    for (int x = 0; x < 9; ++x) w[x] = __ldg(fc_w + x);

    const float* qb = q + (size_t)b * L * D;
    const float* kb = k + (size_t)b * L * D;   // (256, 384) view

    float acc[4][4] = {};

    for (int k0 = 0; k0 < KD; k0 += 64) {
        #pragma unroll
        for (int it = 0; it < 4; ++it) {
            int lin = tid + it * 256;
            int r  = lin >> 4;        // 0..63
            int c4 = lin & 15;        // 0..15
            int kcol = k0 + c4 * 4;   // mult of 4; c constant across the 4
            int c = kcol >> 7;        // 0..2
            int d = kcol & 127;
            const float* qr = qb + (size_t)(3 * (i0 + r)) * D + d;
            float4 q0 = *(const float4*)qr;
            float4 q1 = *(const float4*)(qr + D);
            float4 q2 = *(const float4*)(qr + 2 * D);
            float w0 = w[c], w1 = w[3 + c], w2 = w[6 + c];
            sA[r][c4 * 4 + 0] = w0 * q0.x + w1 * q1.x + w2 * q2.x;
            sA[r][c4 * 4 + 1] = w0 * q0.y + w1 * q1.y + w2 * q2.y;
            sA[r][c4 * 4 + 2] = w0 * q0.z + w1 * q1.z + w2 * q2.z;
            sA[r][c4 * 4 + 3] = w0 * q0.w + w1 * q1.w + w2 * q2.w;
            float4 bv = *(const float4*)(kb + (size_t)(j0 + r) * KD + kcol);
            sB[r][c4 * 4 + 0] = bv.x; sB[r][c4 * 4 + 1] = bv.y;
            sB[r][c4 * 4 + 2] = bv.z; sB[r][c4 * 4 + 3] = bv.w;
        }
        __syncthreads();
        #pragma unroll 8
        for (int kk = 0; kk < 64; ++kk) {
            float a[4], bb[4];
            #pragma unroll
            for (int i = 0; i < 4; ++i) a[i]  = sA[tym * 4 + i][kk];
            #pragma unroll
            for (int j = 0; j < 4; ++j) bb[j] = sB[txn + 16 * j][kk];
            #pragma unroll
            for (int i = 0; i < 4; ++i)
                #pragma unroll
                for (int j = 0; j < 4; ++j) acc[i][j] += a[i] * bb[j];
        }
        __syncthreads();
    }

    const float bias = 128.0f * fc_b[0];
    float* Lbp = g_Lb + (size_t)b * L3 * L3;
    #pragma unroll
    for (int i = 0; i < 4; ++i)
        #pragma unroll
        for (int j = 0; j < 4; ++j)
            Lbp[(size_t)(i0 + tym * 4 + i) * L3 + (j0 + txn + 16 * j)] = acc[i][j] + bias;
}

// ---------------------------------------------------------------------------
// Kernel 2: fused attention, flash-style (no max subtraction — safe range).
// One CTA = (batch b, 32 query rows). 128 threads (4 warps), 2 CTAs/SM.
// 8x4 register micro-tile: warp ty owns q-rows 8*ty..8*ty+7; lane tx covers
// k-cols tx+32j. Per d-step: 2x LDS.128 (q bcast) + 4 scalar LDS -> 32 FFMA.
// SMEM: qT[128][36] | kv[128][129] | eT[128][36] = 102,912 B -> 2 CTAs/SM
// ---------------------------------------------------------------------------
#define SM_QT   0
#define SM_KV   (128 * 36)
#define SM_ST   (128 * 36 + 128 * 129)
#define SMEM_FLOATS (128 * 36 + 128 * 129 + 128 * 36)

__global__ __launch_bounds__(128, 2) void fused_attn_kernel(
    const float* __restrict__ q, const float* __restrict__ k,
    const float* __restrict__ v, float* __restrict__ out,
    float* __restrict__ attn) {
    extern __shared__ float smem[];
    float* sQT = smem + SM_QT;   // [d][m], row stride 36
    float* sKV = smem + SM_KV;   // [n][d], row stride 129
    float* sST = smem + SM_ST;   // [n_local][m], row stride 36

    const int b  = blockIdx.y;
    const int m0 = blockIdx.x * 32;
    const int tid = threadIdx.x;
    const int tx = tid & 31;
    const int ty = tid >> 5;     // warp id 0..3, owns rows 8*ty..8*ty+7

    // ---- load q tile transposed: sQT[d][m] ----
    #pragma unroll
    for (int it = 0; it < 8; ++it) {
        int lin = tid + it * 128;
        int m  = lin >> 5;       // 0..31
        int d4 = lin & 31;
        float4 qv = *(const float4*)(q + (size_t)((b * L + m0 + m) * D) + d4 * 4);
        sQT[(d4 * 4 + 0) * 36 + m] = qv.x;
        sQT[(d4 * 4 + 1) * 36 + m] = qv.y;
        sQT[(d4 * 4 + 2) * 36 + m] = qv.z;
        sQT[(d4 * 4 + 3) * 36 + m] = qv.w;
    }

    const float* Lbp = g_Lb + (size_t)b * L3 * L3;
    float oacc[8][4] = {};
    float rsum[8] = {};

    for (int c = 0; c < 6; ++c) {
        // ---- load K chunk ----
        #pragma unroll
        for (int it = 0; it < 32; ++it) {
            int lin = tid + it * 128;
            int n  = lin >> 5;
            int d4 = lin & 31;
            float4 kv = *(const float4*)(k + (size_t)((b * L + c * 128 + n) * D) + d4 * 4);
            float* dst = sKV + n * 129 + d4 * 4;
            dst[0] = kv.x; dst[1] = kv.y; dst[2] = kv.z; dst[3] = kv.w;
        }
        __syncthreads();

        // ---- S = q @ k^T for this chunk (8x4 micro-tile) ----
        float acc[8][4] = {};
        #pragma unroll 4
        for (int d = 0; d < 128; ++d) {
            float4 qlo = *(const float4*)(sQT + d * 36 + ty * 8);      // bcast
            float4 qhi = *(const float4*)(sQT + d * 36 + ty * 8 + 4);  // bcast
            float qr[8] = {qlo.x, qlo.y, qlo.z, qlo.w, qhi.x, qhi.y, qhi.z, qhi.w};
            float kx[4];
            kx[0] = sKV[(tx      ) * 129 + d];
            kx[1] = sKV[(tx + 32 ) * 129 + d];
            kx[2] = sKV[(tx + 64 ) * 129 + d];
            kx[3] = sKV[(tx + 96 ) * 129 + d];
            #pragma unroll
            for (int i = 0; i < 8; ++i)
                #pragma unroll
                for (int j = 0; j < 4; ++j) acc[i][j] += qr[i] * kx[j];
        }

        // ---- epilogue: e = exp((S + Lb)/T); stash, write attn, rsum ----
        #pragma unroll
        for (int j = 0; j < 4; ++j) {
            int nl = tx + 32 * j;
            int n  = c * 128 + nl;
            int kj = n / 3;
            #pragma unroll
            for (int i = 0; i < 8; ++i) {
                int m  = ty * 8 + i;
                int qi = (m0 + m) / 3;
                float s = (acc[i][j] + Lbp[(size_t)qi * L3 + kj]) * INV_T;
                float e = __expf(s);
                rsum[i] += e;
                sST[nl * 36 + m] = e;
                attn[(size_t)(b * L + m0 + m) * L + n] = e;  // unnormalized
            }
        }
        __syncthreads();

        // ---- load V chunk (reuse sKV) ----
        #pragma unroll
        for (int it = 0; it < 32; ++it) {
            int lin = tid + it * 128;
            int n  = lin >> 5;
            int d4 = lin & 31;
            float4 vv = *(const float4*)(v + (size_t)((b * L + c * 128 + n) * D) + d4 * 4);
            float* dst = sKV + n * 129 + d4 * 4;
            dst[0] = vv.x; dst[1] = vv.y; dst[2] = vv.z; dst[3] = vv.w;
        }
        __syncthreads();

        // ---- O += e @ V over this chunk (8x4 micro-tile) ----
        #pragma unroll 4
        for (int n = 0; n < 128; ++n) {
            float4 plo = *(const float4*)(sST + n * 36 + ty * 8);      // bcast
            float4 phi = *(const float4*)(sST + n * 36 + ty * 8 + 4);  // bcast
            float pr[8] = {plo.x, plo.y, plo.z, plo.w, phi.x, phi.y, phi.z, phi.w};
            float vx[4];
            vx[0] = sKV[n * 129 + tx];
            vx[1] = sKV[n * 129 + tx + 32];
            vx[2] = sKV[n * 129 + tx + 64];
            vx[3] = sKV[n * 129 + tx + 96];
            #pragma unroll
            for (int i = 0; i < 8; ++i)
                #pragma unroll
                for (int j = 0; j < 4; ++j) oacc[i][j] += pr[i] * vx[j];
        }
        __syncthreads();
    }

    // ---- row sums -> inverses (lanes of this warp cover the full row) ----
    float inv[8];
    #pragma unroll
    for (int i = 0; i < 8; ++i) {
        float s = rsum[i];
        #pragma unroll
        for (int o = 16; o; o >>= 1) s += __shfl_xor_sync(0xffffffffu, s, o);
        inv[i] = 1.0f / s;
    }

    // ---- normalize attn strip in place (just-written -> L2 hits) ----
    #pragma unroll
    for (int i = 0; i < 8; ++i) {
        float* arow = attn + (size_t)(b * L + m0 + ty * 8 + i) * L;
        float iv = inv[i];
        #pragma unroll
        for (int t = 0; t < 6; ++t) {
            float4* p = (float4*)arow + tx + 32 * t;
            float4 vv = *p;
            vv.x *= iv; vv.y *= iv; vv.z *= iv; vv.w *= iv;
            *p = vv;
        }
    }

    // ---- normalized output ----
    #pragma unroll
    for (int i = 0; i < 8; ++i) {
        float* orow = out + (size_t)((b * L + m0 + ty * 8 + i) * D);
        float iv = inv[i];
        orow[tx      ] = oacc[i][0] * iv;
        orow[tx + 32 ] = oacc[i][1] * iv;
        orow[tx + 64 ] = oacc[i][2] * iv;
        orow[tx + 96 ] = oacc[i][3] * iv;
    }
}

// ---------------------------------------------------------------------------
extern "C" void kernel_launch(void* const* d_in, const int* in_sizes, int n_in,
                              void* d_out, int out_size) {
    const float* q    = (const float*)d_in[0];
    const float* k    = (const float*)d_in[1];
    const float* v    = (const float*)d_in[2];
    const float* fc_w = (const float*)d_in[3];
    const float* fc_b = (const float*)d_in[4];

    float* out  = (float*)d_out;
    float* attn = out + (size_t)NB * L * D;   // output first, then attn

    lb_kernel<<<dim3(4, 4, NB), 256>>>(q, k, fc_w, fc_b);

    const int smem_bytes = SMEM_FLOATS * sizeof(float);   // 102912
    cudaFuncSetAttribute(fused_attn_kernel,
                         cudaFuncAttributeMaxDynamicSharedMemorySize, smem_bytes);
    fused_attn_kernel<<<dim3(24, NB), 128, smem_bytes>>>(q, k, v, out, attn);
}

// round 6
// speedup vs baseline: 1.2368x; 1.2368x over previous
#include <cuda_runtime.h>

#define NB 16
#define L 768
#define D 128
#define L3 256          // L / CLIP
#define KD 384          // CLIP * D
#define INV_T 0.08838834764831845f   // 1/sqrt(128)

// scratch (allocation-free rule: __device__ globals)
__device__ float g_Lb[NB * L3 * L3];   // [b][i][j]

// ---------------------------------------------------------------------------
// Kernel 1: local block GEMM with fc-weight folding fused into the A loader.
// Lb[b,i,j] = sum_{c,d} qw[b,i,c,d] * kflat[b,j,c,d] + 128*fc_b
// ---------------------------------------------------------------------------
__global__ __launch_bounds__(256) void lb_kernel(const float* __restrict__ q,
                                                 const float* __restrict__ k,
                                                 const float* __restrict__ fc_w,
                                                 const float* __restrict__ fc_b) {
    __shared__ float sA[64][65];
    __shared__ float sB[64][65];
    const int b  = blockIdx.z;
    const int i0 = blockIdx.y * 64;
    const int j0 = blockIdx.x * 64;
    const int tid = threadIdx.x;
    const int txn = tid & 15;    // n dim
    const int tym = tid >> 4;    // m dim

    float w[9];
    #pragma unroll
    for (int x = 0; x < 9; ++x) w[x] = __ldg(fc_w + x);

    const float* qb = q + (size_t)b * L * D;
    const float* kb = k + (size_t)b * L * D;   // (256, 384) view

    float acc[4][4] = {};

    for (int k0 = 0; k0 < KD; k0 += 64) {
        #pragma unroll
        for (int it = 0; it < 4; ++it) {
            int lin = tid + it * 256;
            int r  = lin >> 4;        // 0..63
            int c4 = lin & 15;        // 0..15
            int kcol = k0 + c4 * 4;   // mult of 4; c constant across the 4
            int c = kcol >> 7;        // 0..2
            int d = kcol & 127;
            const float* qr = qb + (size_t)(3 * (i0 + r)) * D + d;
            float4 q0 = *(const float4*)qr;
            float4 q1 = *(const float4*)(qr + D);
            float4 q2 = *(const float4*)(qr + 2 * D);
            float w0 = w[c], w1 = w[3 + c], w2 = w[6 + c];
            sA[r][c4 * 4 + 0] = w0 * q0.x + w1 * q1.x + w2 * q2.x;
            sA[r][c4 * 4 + 1] = w0 * q0.y + w1 * q1.y + w2 * q2.y;
            sA[r][c4 * 4 + 2] = w0 * q0.z + w1 * q1.z + w2 * q2.z;
            sA[r][c4 * 4 + 3] = w0 * q0.w + w1 * q1.w + w2 * q2.w;
            float4 bv = *(const float4*)(kb + (size_t)(j0 + r) * KD + kcol);
            sB[r][c4 * 4 + 0] = bv.x; sB[r][c4 * 4 + 1] = bv.y;
            sB[r][c4 * 4 + 2] = bv.z; sB[r][c4 * 4 + 3] = bv.w;
        }
        __syncthreads();
        #pragma unroll 8
        for (int kk = 0; kk < 64; ++kk) {
            float a[4], bb[4];
            #pragma unroll
            for (int i = 0; i < 4; ++i) a[i]  = sA[tym * 4 + i][kk];
            #pragma unroll
            for (int j = 0; j < 4; ++j) bb[j] = sB[txn + 16 * j][kk];
            #pragma unroll
            for (int i = 0; i < 4; ++i)
                #pragma unroll
                for (int j = 0; j < 4; ++j) acc[i][j] += a[i] * bb[j];
        }
        __syncthreads();
    }

    const float bias = 128.0f * fc_b[0];
    float* Lbp = g_Lb + (size_t)b * L3 * L3;
    #pragma unroll
    for (int i = 0; i < 4; ++i)
        #pragma unroll
        for (int j = 0; j < 4; ++j)
            Lbp[(size_t)(i0 + tym * 4 + i) * L3 + (j0 + txn + 16 * j)] = acc[i][j] + bias;
}

// ---------------------------------------------------------------------------
// Kernel 2: fused attention, flash-style (no max subtraction — safe range).
// One CTA = (batch b, 32 query rows). 256 threads (8 warps), 3 CTAs/SM ->
// grid 384 fits in ONE wave (148*3 = 444 slots).
// K/V chunk = 64 columns (12 chunks). Micro-tiles: phase1 acc[4][2],
// phase2 oacc[4][4]. Warp ty owns q-rows 4*ty..4*ty+3.
// SMEM: qT[128][36] | kv[64][129] | eT[64][36] = 60,672 B -> 3 CTAs/SM
// ---------------------------------------------------------------------------
#define CH 64
#define NCH 12
#define SM_QT   0
#define SM_KV   (128 * 36)
#define SM_ST   (128 * 36 + CH * 129)
#define SMEM_FLOATS (128 * 36 + CH * 129 + CH * 36)

__global__ __launch_bounds__(256, 3) void fused_attn_kernel(
    const float* __restrict__ q, const float* __restrict__ k,
    const float* __restrict__ v, float* __restrict__ out,
    float* __restrict__ attn) {
    extern __shared__ float smem[];
    float* sQT = smem + SM_QT;   // [d][m], row stride 36
    float* sKV = smem + SM_KV;   // [n_local][d], row stride 129
    float* sST = smem + SM_ST;   // [n_local][m], row stride 36

    const int b  = blockIdx.y;
    const int m0 = blockIdx.x * 32;
    const int tid = threadIdx.x;
    const int tx = tid & 31;
    const int ty = tid >> 5;     // warp id 0..7, owns rows 4*ty..4*ty+3

    // ---- load q tile transposed: sQT[d][m] ----
    #pragma unroll
    for (int it = 0; it < 4; ++it) {
        int lin = tid + it * 256;
        int m  = lin >> 5;       // 0..31
        int d4 = lin & 31;
        float4 qv = *(const float4*)(q + (size_t)((b * L + m0 + m) * D) + d4 * 4);
        sQT[(d4 * 4 + 0) * 36 + m] = qv.x;
        sQT[(d4 * 4 + 1) * 36 + m] = qv.y;
        sQT[(d4 * 4 + 2) * 36 + m] = qv.z;
        sQT[(d4 * 4 + 3) * 36 + m] = qv.w;
    }

    const float* Lbp = g_Lb + (size_t)b * L3 * L3;
    float oacc[4][4] = {};
    float rsum[4] = {};

    for (int c = 0; c < NCH; ++c) {
        // ---- load K chunk (64 rows x 128) ----
        #pragma unroll
        for (int it = 0; it < 8; ++it) {
            int lin = tid + it * 256;
            int n  = lin >> 5;       // 0..63
            int d4 = lin & 31;
            float4 kv = *(const float4*)(k + (size_t)((b * L + c * CH + n) * D) + d4 * 4);
            float* dst = sKV + n * 129 + d4 * 4;
            dst[0] = kv.x; dst[1] = kv.y; dst[2] = kv.z; dst[3] = kv.w;
        }
        __syncthreads();

        // ---- S = q @ k^T for this chunk (4x2 micro-tile) ----
        float acc[4][2] = {};
        #pragma unroll 4
        for (int d = 0; d < 128; ++d) {
            float4 qv = *(const float4*)(sQT + d * 36 + ty * 4);  // broadcast
            float kx0 = sKV[(tx      ) * 129 + d];
            float kx1 = sKV[(tx + 32 ) * 129 + d];
            acc[0][0] += qv.x * kx0; acc[0][1] += qv.x * kx1;
            acc[1][0] += qv.y * kx0; acc[1][1] += qv.y * kx1;
            acc[2][0] += qv.z * kx0; acc[2][1] += qv.z * kx1;
            acc[3][0] += qv.w * kx0; acc[3][1] += qv.w * kx1;
        }

        // ---- epilogue: e = exp((S + Lb)/T); stash, write attn, rsum ----
        #pragma unroll
        for (int j = 0; j < 2; ++j) {
            int nl = tx + 32 * j;
            int n  = c * CH + nl;
            int kj = n / 3;
            #pragma unroll
            for (int i = 0; i < 4; ++i) {
                int m  = ty * 4 + i;
                int qi = (m0 + m) / 3;
                float s = (acc[i][j] + Lbp[(size_t)qi * L3 + kj]) * INV_T;
                float e = __expf(s);
                rsum[i] += e;
                sST[nl * 36 + m] = e;
                attn[(size_t)(b * L + m0 + m) * L + n] = e;  // unnormalized
            }
        }
        __syncthreads();

        // ---- load V chunk (reuse sKV) ----
        #pragma unroll
        for (int it = 0; it < 8; ++it) {
            int lin = tid + it * 256;
            int n  = lin >> 5;
            int d4 = lin & 31;
            float4 vv = *(const float4*)(v + (size_t)((b * L + c * CH + n) * D) + d4 * 4);
            float* dst = sKV + n * 129 + d4 * 4;
            dst[0] = vv.x; dst[1] = vv.y; dst[2] = vv.z; dst[3] = vv.w;
        }
        __syncthreads();

        // ---- O += e @ V over this chunk (4x4 micro-tile) ----
        #pragma unroll 4
        for (int n = 0; n < CH; ++n) {
            float4 pv = *(const float4*)(sST + n * 36 + ty * 4);  // broadcast
            float vx0 = sKV[n * 129 + tx];
            float vx1 = sKV[n * 129 + tx + 32];
            float vx2 = sKV[n * 129 + tx + 64];
            float vx3 = sKV[n * 129 + tx + 96];
            oacc[0][0] += pv.x * vx0; oacc[0][1] += pv.x * vx1;
            oacc[0][2] += pv.x * vx2; oacc[0][3] += pv.x * vx3;
            oacc[1][0] += pv.y * vx0; oacc[1][1] += pv.y * vx1;
            oacc[1][2] += pv.y * vx2; oacc[1][3] += pv.y * vx3;
            oacc[2][0] += pv.z * vx0; oacc[2][1] += pv.z * vx1;
            oacc[2][2] += pv.z * vx2; oacc[2][3] += pv.z * vx3;
            oacc[3][0] += pv.w * vx0; oacc[3][1] += pv.w * vx1;
            oacc[3][2] += pv.w * vx2; oacc[3][3] += pv.w * vx3;
        }
        __syncthreads();
    }

    // ---- row sums -> inverses (lanes of this warp cover the full row) ----
    float inv[4];
    #pragma unroll
    for (int i = 0; i < 4; ++i) {
        float s = rsum[i];
        #pragma unroll
        for (int o = 16; o; o >>= 1) s += __shfl_xor_sync(0xffffffffu, s, o);
        inv[i] = 1.0f / s;
    }

    // ---- normalize attn strip in place (just-written -> L2 hits) ----
    #pragma unroll
    for (int i = 0; i < 4; ++i) {
        float* arow = attn + (size_t)(b * L + m0 + ty * 4 + i) * L;
        float iv = inv[i];
        #pragma unroll
        for (int t = 0; t < 6; ++t) {
            float4* p = (float4*)arow + tx + 32 * t;
            float4 vv = *p;
            vv.x *= iv; vv.y *= iv; vv.z *= iv; vv.w *= iv;
            *p = vv;
        }
    }

    // ---- normalized output ----
    #pragma unroll
    for (int i = 0; i < 4; ++i) {
        float* orow = out + (size_t)((b * L + m0 + ty * 4 + i) * D);
        float iv = inv[i];
        orow[tx      ] = oacc[i][0] * iv;
        orow[tx + 32 ] = oacc[i][1] * iv;
        orow[tx + 64 ] = oacc[i][2] * iv;
        orow[tx + 96 ] = oacc[i][3] * iv;
    }
}

// ---------------------------------------------------------------------------
extern "C" void kernel_launch(void* const* d_in, const int* in_sizes, int n_in,
                              void* d_out, int out_size) {
    const float* q    = (const float*)d_in[0];
    const float* k    = (const float*)d_in[1];
    const float* v    = (const float*)d_in[2];
    const float* fc_w = (const float*)d_in[3];
    const float* fc_b = (const float*)d_in[4];

    float* out  = (float*)d_out;
    float* attn = out + (size_t)NB * L * D;   // output first, then attn

    lb_kernel<<<dim3(4, 4, NB), 256>>>(q, k, fc_w, fc_b);

    const int smem_bytes = SMEM_FLOATS * sizeof(float);   // 60672
    cudaFuncSetAttribute(fused_attn_kernel,
                         cudaFuncAttributeMaxDynamicSharedMemorySize, smem_bytes);
    fused_attn_kernel<<<dim3(24, NB), 256, smem_bytes>>>(q, k, v, out, attn);
}

// round 7
// speedup vs baseline: 1.4431x; 1.1668x over previous
#include <cuda_runtime.h>

#define NB 16
#define L 768
#define D 128
#define L3 256          // L / CLIP
#define KD 384          // CLIP * D
#define INV_T 0.08838834764831845f   // 1/sqrt(128)

// scratch (allocation-free rule: __device__ globals)
__device__ float g_Lb[NB * L3 * L3];   // [b][i][j]

// ---------------------------------------------------------------------------
// Kernel 1: local block GEMM with fc-weight folding fused into the A loader.
// Lb[b,i,j] = sum_{c,d} qw[b,i,c,d] * kflat[b,j,c,d] + 128*fc_b
// ---------------------------------------------------------------------------
__global__ __launch_bounds__(256) void lb_kernel(const float* __restrict__ q,
                                                 const float* __restrict__ k,
                                                 const float* __restrict__ fc_w,
                                                 const float* __restrict__ fc_b) {
    __shared__ float sA[64][65];
    __shared__ float sB[64][65];
    const int b  = blockIdx.z;
    const int i0 = blockIdx.y * 64;
    const int j0 = blockIdx.x * 64;
    const int tid = threadIdx.x;
    const int txn = tid & 15;    // n dim
    const int tym = tid >> 4;    // m dim

    float w[9];
    #pragma unroll
    for (int x = 0; x < 9; ++x) w[x] = __ldg(fc_w + x);

    const float* qb = q + (size_t)b * L * D;
    const float* kb = k + (size_t)b * L * D;   // (256, 384) view

    float acc[4][4] = {};

    for (int k0 = 0; k0 < KD; k0 += 64) {
        #pragma unroll
        for (int it = 0; it < 4; ++it) {
            int lin = tid + it * 256;
            int r  = lin >> 4;        // 0..63
            int c4 = lin & 15;        // 0..15
            int kcol = k0 + c4 * 4;   // mult of 4; c constant across the 4
            int c = kcol >> 7;        // 0..2
            int d = kcol & 127;
            const float* qr = qb + (size_t)(3 * (i0 + r)) * D + d;
            float4 q0 = *(const float4*)qr;
            float4 q1 = *(const float4*)(qr + D);
            float4 q2 = *(const float4*)(qr + 2 * D);
            float w0 = w[c], w1 = w[3 + c], w2 = w[6 + c];
            sA[r][c4 * 4 + 0] = w0 * q0.x + w1 * q1.x + w2 * q2.x;
            sA[r][c4 * 4 + 1] = w0 * q0.y + w1 * q1.y + w2 * q2.y;
            sA[r][c4 * 4 + 2] = w0 * q0.z + w1 * q1.z + w2 * q2.z;
            sA[r][c4 * 4 + 3] = w0 * q0.w + w1 * q1.w + w2 * q2.w;
            float4 bv = *(const float4*)(kb + (size_t)(j0 + r) * KD + kcol);
            sB[r][c4 * 4 + 0] = bv.x; sB[r][c4 * 4 + 1] = bv.y;
            sB[r][c4 * 4 + 2] = bv.z; sB[r][c4 * 4 + 3] = bv.w;
        }
        __syncthreads();
        #pragma unroll 8
        for (int kk = 0; kk < 64; ++kk) {
            float a[4], bb[4];
            #pragma unroll
            for (int i = 0; i < 4; ++i) a[i]  = sA[tym * 4 + i][kk];
            #pragma unroll
            for (int j = 0; j < 4; ++j) bb[j] = sB[txn + 16 * j][kk];
            #pragma unroll
            for (int i = 0; i < 4; ++i)
                #pragma unroll
                for (int j = 0; j < 4; ++j) acc[i][j] += a[i] * bb[j];
        }
        __syncthreads();
    }

    const float bias = 128.0f * fc_b[0];
    float* Lbp = g_Lb + (size_t)b * L3 * L3;
    #pragma unroll
    for (int i = 0; i < 4; ++i)
        #pragma unroll
        for (int j = 0; j < 4; ++j)
            Lbp[(size_t)(i0 + tym * 4 + i) * L3 + (j0 + txn + 16 * j)] = acc[i][j] + bias;
}

// ---------------------------------------------------------------------------
// Kernel 2: fused attention, flash-style (no max subtraction — safe range).
// One CTA = (batch b, 32 query rows). 256 threads (8 warps), 3 CTAs/SM.
// K/V chunk = 64 cols. LDS.128-vectorized contraction:
//   phase1: per 4-d group: 2 vec k loads + 4 vec q broadcasts -> 32 FFMA
//   phase2: per n: 1 vec pv broadcast + 1 vec v load -> 16 FFMA
// Lane tx owns contiguous d-cols tx*4..tx*4+3 in phase 2 (STG.128 out).
// SMEM: qT[128][36] | kv[64][132] | eT[64][36] = 61,440 B -> 3 CTAs/SM
// ---------------------------------------------------------------------------
#define CH 64
#define NCH 12
#define KVP 132   // kv row stride (16B-aligned, banks 4*tx+d conflict-free)
#define SM_QT   0
#define SM_KV   (128 * 36)
#define SM_ST   (128 * 36 + CH * KVP)
#define SMEM_FLOATS (128 * 36 + CH * KVP + CH * 36)

__global__ __launch_bounds__(256, 3) void fused_attn_kernel(
    const float* __restrict__ q, const float* __restrict__ k,
    const float* __restrict__ v, float* __restrict__ out,
    float* __restrict__ attn) {
    extern __shared__ float smem[];
    float* sQT = smem + SM_QT;   // [d][m], row stride 36
    float* sKV = smem + SM_KV;   // [n_local][d], row stride 132
    float* sST = smem + SM_ST;   // [n_local][m], row stride 36

    const int b  = blockIdx.y;
    const int m0 = blockIdx.x * 32;
    const int tid = threadIdx.x;
    const int tx = tid & 31;
    const int ty = tid >> 5;     // warp id 0..7, owns rows 4*ty..4*ty+3

    // ---- load q tile transposed: sQT[d][m] ----
    #pragma unroll
    for (int it = 0; it < 4; ++it) {
        int lin = tid + it * 256;
        int m  = lin >> 5;       // 0..31
        int d4 = lin & 31;
        float4 qv = *(const float4*)(q + (size_t)((b * L + m0 + m) * D) + d4 * 4);
        sQT[(d4 * 4 + 0) * 36 + m] = qv.x;
        sQT[(d4 * 4 + 1) * 36 + m] = qv.y;
        sQT[(d4 * 4 + 2) * 36 + m] = qv.z;
        sQT[(d4 * 4 + 3) * 36 + m] = qv.w;
    }

    const float* Lbp = g_Lb + (size_t)b * L3 * L3;
    float4 oacc[4] = {};                 // [m_i] x 4 contiguous d-cols
    float rsum[4] = {};

    for (int c = 0; c < NCH; ++c) {
        // ---- load K chunk (64 rows x 128) ----
        #pragma unroll
        for (int it = 0; it < 8; ++it) {
            int lin = tid + it * 256;
            int n  = lin >> 5;       // 0..63
            int d4 = lin & 31;
            float4 kv = *(const float4*)(k + (size_t)((b * L + c * CH + n) * D) + d4 * 4);
            *(float4*)(sKV + n * KVP + d4 * 4) = kv;
        }
        __syncthreads();

        // ---- S = q @ k^T for this chunk (4x2, d vectorized by 4) ----
        float acc[4][2] = {};
        #pragma unroll 2
        for (int dg = 0; dg < 128; dg += 4) {
            float4 ka = *(const float4*)(sKV + (tx      ) * KVP + dg);
            float4 kc = *(const float4*)(sKV + (tx + 32 ) * KVP + dg);
            const float* kaf = (const float*)&ka;
            const float* kcf = (const float*)&kc;
            #pragma unroll
            for (int dd = 0; dd < 4; ++dd) {
                float4 qv = *(const float4*)(sQT + (dg + dd) * 36 + ty * 4);  // bcast
                float k0 = kaf[dd], k1 = kcf[dd];
                acc[0][0] += qv.x * k0; acc[0][1] += qv.x * k1;
                acc[1][0] += qv.y * k0; acc[1][1] += qv.y * k1;
                acc[2][0] += qv.z * k0; acc[2][1] += qv.z * k1;
                acc[3][0] += qv.w * k0; acc[3][1] += qv.w * k1;
            }
        }

        // ---- epilogue: e = exp((S + Lb)/T); stash, write attn, rsum ----
        #pragma unroll
        for (int j = 0; j < 2; ++j) {
            int nl = tx + 32 * j;
            int n  = c * CH + nl;
            int kj = n / 3;
            #pragma unroll
            for (int i = 0; i < 4; ++i) {
                int m  = ty * 4 + i;
                int qi = (m0 + m) / 3;
                float s = (acc[i][j] + Lbp[(size_t)qi * L3 + kj]) * INV_T;
                float e = __expf(s);
                rsum[i] += e;
                sST[nl * 36 + m] = e;
                attn[(size_t)(b * L + m0 + m) * L + n] = e;  // unnormalized
            }
        }
        __syncthreads();

        // ---- load V chunk (reuse sKV) ----
        #pragma unroll
        for (int it = 0; it < 8; ++it) {
            int lin = tid + it * 256;
            int n  = lin >> 5;
            int d4 = lin & 31;
            float4 vv = *(const float4*)(v + (size_t)((b * L + c * CH + n) * D) + d4 * 4);
            *(float4*)(sKV + n * KVP + d4 * 4) = vv;
        }
        __syncthreads();

        // ---- O += e @ V (lane owns d-cols tx*4..tx*4+3, vectorized) ----
        #pragma unroll 4
        for (int n = 0; n < CH; ++n) {
            float4 pv = *(const float4*)(sST + n * 36 + ty * 4);       // bcast
            float4 vv = *(const float4*)(sKV + n * KVP + tx * 4);
            oacc[0].x += pv.x * vv.x; oacc[0].y += pv.x * vv.y;
            oacc[0].z += pv.x * vv.z; oacc[0].w += pv.x * vv.w;
            oacc[1].x += pv.y * vv.x; oacc[1].y += pv.y * vv.y;
            oacc[1].z += pv.y * vv.z; oacc[1].w += pv.y * vv.w;
            oacc[2].x += pv.z * vv.x; oacc[2].y += pv.z * vv.y;
            oacc[2].z += pv.z * vv.z; oacc[2].w += pv.z * vv.w;
            oacc[3].x += pv.w * vv.x; oacc[3].y += pv.w * vv.y;
            oacc[3].z += pv.w * vv.z; oacc[3].w += pv.w * vv.w;
        }
        __syncthreads();
    }

    // ---- row sums -> inverses (lanes of this warp cover the full row) ----
    float inv[4];
    #pragma unroll
    for (int i = 0; i < 4; ++i) {
        float s = rsum[i];
        #pragma unroll
        for (int o = 16; o; o >>= 1) s += __shfl_xor_sync(0xffffffffu, s, o);
        inv[i] = 1.0f / s;
    }

    // ---- normalize attn strip in place (just-written -> L2 hits) ----
    #pragma unroll
    for (int i = 0; i < 4; ++i) {
        float* arow = attn + (size_t)(b * L + m0 + ty * 4 + i) * L;
        float iv = inv[i];
        #pragma unroll
        for (int t = 0; t < 6; ++t) {
            float4* p = (float4*)arow + tx + 32 * t;
            float4 vv = *p;
            vv.x *= iv; vv.y *= iv; vv.z *= iv; vv.w *= iv;
            *p = vv;
        }
    }

    // ---- normalized output (STG.128) ----
    #pragma unroll
    for (int i = 0; i < 4; ++i) {
        float* orow = out + (size_t)((b * L + m0 + ty * 4 + i) * D);
        float iv = inv[i];
        float4 o = oacc[i];
        o.x *= iv; o.y *= iv; o.z *= iv; o.w *= iv;
        *(float4*)(orow + tx * 4) = o;
    }
}

// ---------------------------------------------------------------------------
extern "C" void kernel_launch(void* const* d_in, const int* in_sizes, int n_in,
                              void* d_out, int out_size) {
    const float* q    = (const float*)d_in[0];
    const float* k    = (const float*)d_in[1];
    const float* v    = (const float*)d_in[2];
    const float* fc_w = (const float*)d_in[3];
    const float* fc_b = (const float*)d_in[4];

    float* out  = (float*)d_out;
    float* attn = out + (size_t)NB * L * D;   // output first, then attn

    lb_kernel<<<dim3(4, 4, NB), 256>>>(q, k, fc_w, fc_b);

    const int smem_bytes = SMEM_FLOATS * sizeof(float);   // 61440
    cudaFuncSetAttribute(fused_attn_kernel,
                         cudaFuncAttributeMaxDynamicSharedMemorySize, smem_bytes);
    fused_attn_kernel<<<dim3(24, NB), 256, smem_bytes>>>(q, k, v, out, attn);
}

// round 8
// speedup vs baseline: 1.5297x; 1.0601x over previous
#include <cuda_runtime.h>

#define NB 16
#define L 768
#define D 128
#define L3 256          // L / CLIP
#define KD 384          // CLIP * D
#define INV_T 0.08838834764831845f   // 1/sqrt(128)

// scratch (allocation-free rule: __device__ globals); +512 pad for sLB overread
__device__ float g_Lb[NB * L3 * L3 + 512];

typedef unsigned long long u64;

__device__ __forceinline__ u64 pk2(float x, float y) {
    u64 r; asm("mov.b64 %0,{%1,%2};" : "=l"(r) : "f"(x), "f"(y)); return r;
}
__device__ __forceinline__ float2 upk2(u64 v) {
    float2 f; asm("mov.b64 {%0,%1},%2;" : "=f"(f.x), "=f"(f.y) : "l"(v)); return f;
}
#define FMA2(acc, a, b) \
    asm("fma.rn.f32x2 %0,%1,%2,%0;" : "+l"(acc) : "l"(a), "l"(b))

// ---------------------------------------------------------------------------
// Kernel 1: local block GEMM with fc-weight folding fused into the A loader.
// Lb[b,i,j] = sum_{c,d} qw[b,i,c,d] * kflat[b,j,c,d] + 128*fc_b
// ---------------------------------------------------------------------------
__global__ __launch_bounds__(256) void lb_kernel(const float* __restrict__ q,
                                                 const float* __restrict__ k,
                                                 const float* __restrict__ fc_w,
                                                 const float* __restrict__ fc_b) {
    __shared__ float sA[64][65];
    __shared__ float sB[64][65];
    const int b  = blockIdx.z;
    const int i0 = blockIdx.y * 64;
    const int j0 = blockIdx.x * 64;
    const int tid = threadIdx.x;
    const int txn = tid & 15;    // n dim
    const int tym = tid >> 4;    // m dim

    float w[9];
    #pragma unroll
    for (int x = 0; x < 9; ++x) w[x] = __ldg(fc_w + x);

    const float* qb = q + (size_t)b * L * D;
    const float* kb = k + (size_t)b * L * D;   // (256, 384) view

    float acc[4][4] = {};

    for (int k0 = 0; k0 < KD; k0 += 64) {
        #pragma unroll
        for (int it = 0; it < 4; ++it) {
            int lin = tid + it * 256;
            int r  = lin >> 4;        // 0..63
            int c4 = lin & 15;        // 0..15
            int kcol = k0 + c4 * 4;
            int c = kcol >> 7;
            int d = kcol & 127;
            const float* qr = qb + (size_t)(3 * (i0 + r)) * D + d;
            float4 q0 = *(const float4*)qr;
            float4 q1 = *(const float4*)(qr + D);
            float4 q2 = *(const float4*)(qr + 2 * D);
            float w0 = w[c], w1 = w[3 + c], w2 = w[6 + c];
            sA[r][c4 * 4 + 0] = w0 * q0.x + w1 * q1.x + w2 * q2.x;
            sA[r][c4 * 4 + 1] = w0 * q0.y + w1 * q1.y + w2 * q2.y;
            sA[r][c4 * 4 + 2] = w0 * q0.z + w1 * q1.z + w2 * q2.z;
            sA[r][c4 * 4 + 3] = w0 * q0.w + w1 * q1.w + w2 * q2.w;
            float4 bv = *(const float4*)(kb + (size_t)(j0 + r) * KD + kcol);
            sB[r][c4 * 4 + 0] = bv.x; sB[r][c4 * 4 + 1] = bv.y;
            sB[r][c4 * 4 + 2] = bv.z; sB[r][c4 * 4 + 3] = bv.w;
        }
        __syncthreads();
        #pragma unroll 8
        for (int kk = 0; kk < 64; ++kk) {
            float a[4], bb[4];
            #pragma unroll
            for (int i = 0; i < 4; ++i) a[i]  = sA[tym * 4 + i][kk];
            #pragma unroll
            for (int j = 0; j < 4; ++j) bb[j] = sB[txn + 16 * j][kk];
            #pragma unroll
            for (int i = 0; i < 4; ++i)
                #pragma unroll
                for (int j = 0; j < 4; ++j) acc[i][j] += a[i] * bb[j];
        }
        __syncthreads();
    }

    const float bias = 128.0f * fc_b[0];
    float* Lbp = g_Lb + (size_t)b * L3 * L3;
    #pragma unroll
    for (int i = 0; i < 4; ++i)
        #pragma unroll
        for (int j = 0; j < 4; ++j)
            Lbp[(size_t)(i0 + tym * 4 + i) * L3 + (j0 + txn + 16 * j)] = acc[i][j] + bias;
}

// ---------------------------------------------------------------------------
// Kernel 2: fused attention, flash-style, packed f32x2 FMA.
// One CTA = (batch b, 32 query rows). 128 threads (4 warps), 3 CTAs/SM.
// Warp ty owns q-rows 8*ty..8*ty+7. K/V chunk = 64 cols (12 chunks).
// Phase1 pairs the d-dim (q stored [m][d] so LDS.128 gives 2 operand pairs);
// phase2 pairs the output d-cols (v natural layout; e splatted).
// SMEM: sQ[32][132] | sKV[64][132] | sST[64][36] | sLB[12][256]
//       = 72,192 B -> 3 CTAs/SM.
// ---------------------------------------------------------------------------
#define CH 64
#define NCH 12
#define KVP 132
#define SM_Q    0
#define SM_KV   (32 * KVP)
#define SM_ST   (32 * KVP + CH * KVP)
#define SM_LB   (32 * KVP + CH * KVP + CH * 36)
#define SMEM_FLOATS (32 * KVP + CH * KVP + CH * 36 + 12 * 256)

__global__ __launch_bounds__(128, 3) void fused_attn_kernel(
    const float* __restrict__ q, const float* __restrict__ k,
    const float* __restrict__ v, float* __restrict__ out,
    float* __restrict__ attn) {
    extern __shared__ float smem[];
    float* sQ  = smem + SM_Q;    // [m][d], row stride 132
    float* sKV = smem + SM_KV;   // [n_local][d], row stride 132
    float* sST = smem + SM_ST;   // [n_local][m], row stride 36
    float* sLB = smem + SM_LB;   // [qrel][kj], row stride 256

    const int b  = blockIdx.y;
    const int m0 = blockIdx.x * 32;
    const int tid = threadIdx.x;
    const int tx = tid & 31;
    const int ty = tid >> 5;     // warp id 0..3, owns rows 8*ty..8*ty+7
    const int qi0 = m0 / 3;

    // ---- load q tile [m][d] (natural layout, coalesced, conflict-free) ----
    #pragma unroll
    for (int it = 0; it < 8; ++it) {
        int lin = tid + it * 128;
        int m  = lin >> 5;       // 0..31
        int d4 = lin & 31;
        float4 qv = *(const float4*)(q + (size_t)((b * L + m0 + m) * D) + d4 * 4);
        *(float4*)(sQ + m * KVP + d4 * 4) = qv;
    }
    // ---- stage the 12 Lb rows this CTA needs ----
    {
        const float* Lbp = g_Lb + (size_t)b * L3 * L3 + (size_t)qi0 * L3;
        #pragma unroll
        for (int it = 0; it < 6; ++it) {
            int lin = tid + it * 128;          // 0..767 -> 12 rows x 64 f4
            *(float4*)(sLB + lin * 4) = *(const float4*)(Lbp + lin * 4);
        }
    }

    int qrel[8];
    #pragma unroll
    for (int i = 0; i < 8; ++i) qrel[i] = (m0 + ty * 8 + i) / 3 - qi0;

    u64 oacc[8][2] = {};     // [m_i][dcol pair], pairs over output cols
    float rsum[8] = {};

    for (int c = 0; c < NCH; ++c) {
        // ---- load K chunk ----
        #pragma unroll
        for (int it = 0; it < 16; ++it) {
            int lin = tid + it * 128;
            int n  = lin >> 5;       // 0..63
            int d4 = lin & 31;
            float4 kv = *(const float4*)(k + (size_t)((b * L + c * CH + n) * D) + d4 * 4);
            *(float4*)(sKV + n * KVP + d4 * 4) = kv;
        }
        __syncthreads();

        // ---- S = q @ k^T (m=8, j=2, d paired via f32x2) ----
        u64 acc[8][2] = {};
        #pragma unroll 2
        for (int dg = 0; dg < 128; dg += 4) {
            ulonglong2 ka = *(const ulonglong2*)(sKV + (tx      ) * KVP + dg);
            ulonglong2 kc = *(const ulonglong2*)(sKV + (tx + 32 ) * KVP + dg);
            #pragma unroll
            for (int i = 0; i < 8; ++i) {
                ulonglong2 qp = *(const ulonglong2*)(sQ + (ty * 8 + i) * KVP + dg); // bcast
                FMA2(acc[i][0], qp.x, ka.x);
                FMA2(acc[i][0], qp.y, ka.y);
                FMA2(acc[i][1], qp.x, kc.x);
                FMA2(acc[i][1], qp.y, kc.y);
            }
        }

        // ---- epilogue: e = exp((lo+hi + Lb)/T); stash, write attn, rsum ----
        #pragma unroll
        for (int j = 0; j < 2; ++j) {
            int nl = tx + 32 * j;
            int n  = c * CH + nl;
            int kj = n / 3;
            #pragma unroll
            for (int i = 0; i < 8; ++i) {
                float2 a = upk2(acc[i][j]);
                float s = (a.x + a.y + sLB[qrel[i] * 256 + kj]) * INV_T;
                float e = __expf(s);
                rsum[i] += e;
                sST[nl * 36 + ty * 8 + i] = e;
                attn[(size_t)(b * L + m0 + ty * 8 + i) * L + n] = e;  // unnorm
            }
        }
        __syncthreads();

        // ---- load V chunk (reuse sKV) ----
        #pragma unroll
        for (int it = 0; it < 16; ++it) {
            int lin = tid + it * 128;
            int n  = lin >> 5;
            int d4 = lin & 31;
            float4 vv = *(const float4*)(v + (size_t)((b * L + c * CH + n) * D) + d4 * 4);
            *(float4*)(sKV + n * KVP + d4 * 4) = vv;
        }
        __syncthreads();

        // ---- O += e @ V (lane owns d-cols tx*4..tx*4+3 as 2 pairs) ----
        #pragma unroll 2
        for (int n = 0; n < CH; ++n) {
            float4 elo = *(const float4*)(sST + n * 36 + ty * 8);      // bcast
            float4 ehi = *(const float4*)(sST + n * 36 + ty * 8 + 4);  // bcast
            ulonglong2 vv = *(const ulonglong2*)(sKV + n * KVP + tx * 4);
            u64 es;
            es = pk2(elo.x, elo.x); FMA2(oacc[0][0], es, vv.x); FMA2(oacc[0][1], es, vv.y);
            es = pk2(elo.y, elo.y); FMA2(oacc[1][0], es, vv.x); FMA2(oacc[1][1], es, vv.y);
            es = pk2(elo.z, elo.z); FMA2(oacc[2][0], es, vv.x); FMA2(oacc[2][1], es, vv.y);
            es = pk2(elo.w, elo.w); FMA2(oacc[3][0], es, vv.x); FMA2(oacc[3][1], es, vv.y);
            es = pk2(ehi.x, ehi.x); FMA2(oacc[4][0], es, vv.x); FMA2(oacc[4][1], es, vv.y);
            es = pk2(ehi.y, ehi.y); FMA2(oacc[5][0], es, vv.x); FMA2(oacc[5][1], es, vv.y);
            es = pk2(ehi.z, ehi.z); FMA2(oacc[6][0], es, vv.x); FMA2(oacc[6][1], es, vv.y);
            es = pk2(ehi.w, ehi.w); FMA2(oacc[7][0], es, vv.x); FMA2(oacc[7][1], es, vv.y);
        }
        __syncthreads();
    }

    // ---- row sums -> inverses (lanes of this warp cover the full row) ----
    float inv[8];
    #pragma unroll
    for (int i = 0; i < 8; ++i) {
        float s = rsum[i];
        #pragma unroll
        for (int o = 16; o; o >>= 1) s += __shfl_xor_sync(0xffffffffu, s, o);
        inv[i] = 1.0f / s;
    }

    // ---- normalize attn strip in place (just-written -> L2 hits) ----
    #pragma unroll
    for (int i = 0; i < 8; ++i) {
        float* arow = attn + (size_t)(b * L + m0 + ty * 8 + i) * L;
        float iv = inv[i];
        #pragma unroll
        for (int t = 0; t < 6; ++t) {
            float4* p = (float4*)arow + tx + 32 * t;
            float4 vv = *p;
            vv.x *= iv; vv.y *= iv; vv.z *= iv; vv.w *= iv;
            *p = vv;
        }
    }

    // ---- normalized output (STG.128) ----
    #pragma unroll
    for (int i = 0; i < 8; ++i) {
        float* orow = out + (size_t)((b * L + m0 + ty * 8 + i) * D);
        float iv = inv[i];
        float2 p0 = upk2(oacc[i][0]);
        float2 p1 = upk2(oacc[i][1]);
        float4 o = make_float4(p0.x * iv, p0.y * iv, p1.x * iv, p1.y * iv);
        *(float4*)(orow + tx * 4) = o;
    }
}

// ---------------------------------------------------------------------------
extern "C" void kernel_launch(void* const* d_in, const int* in_sizes, int n_in,
                              void* d_out, int out_size) {
    const float* q    = (const float*)d_in[0];
    const float* k    = (const float*)d_in[1];
    const float* v    = (const float*)d_in[2];
    const float* fc_w = (const float*)d_in[3];
    const float* fc_b = (const float*)d_in[4];

    float* out  = (float*)d_out;
    float* attn = out + (size_t)NB * L * D;   // output first, then attn

    lb_kernel<<<dim3(4, 4, NB), 256>>>(q, k, fc_w, fc_b);

    const int smem_bytes = SMEM_FLOATS * sizeof(float);   // 72192
    cudaFuncSetAttribute(fused_attn_kernel,
                         cudaFuncAttributeMaxDynamicSharedMemorySize, smem_bytes);
    fused_attn_kernel<<<dim3(24, NB), 128, smem_bytes>>>(q, k, v, out, attn);
}